// round 13
// baseline (speedup 1.0000x reference)
#include <cuda_runtime.h>
#include <cuda_fp16.h>
#include <cstdint>
#include <math.h>

// Problem constants
#define BB    2
#define TT    32
#define HH    18
#define WW    32
#define DIM   1024
#define HEADS 16
#define HD    64
#define HWP   (HH*WW)            // 576
#define MTOK  (BB*TT*HWP)        // 36864 tokens
#define EQKV  (3*HEADS*HD)       // 3072
#define EO    (HEADS*HD)         // 1024

// ---------------- scratch (device globals; no allocation allowed) ----------
__device__ float   g_qkv[(size_t)MTOK * EQKV];
__device__ __half  g_x_hi[(size_t)MTOK * DIM];
__device__ __half  g_x_lo[(size_t)MTOK * DIM];
__device__ __half  g_wq[(size_t)EQKV * DIM];
__device__ __half  g_wo[(size_t)DIM * DIM];
__device__ __half  g_att_hi[(size_t)MTOK * EO];
__device__ __half  g_att_lo[(size_t)MTOK * EO];

// ---------------- helpers ---------------------------------------------------
__device__ __forceinline__ uint32_t smem_u32(const void* p) {
    uint32_t a;
    asm("{ .reg .u64 t; cvta.to.shared.u64 t, %1; cvt.u32.u64 %0, t; }" : "=r"(a) : "l"(p));
    return a;
}

// SW64 swizzle: 64-byte rows, 8-row/512B atom
#define SWZ64(off) ((off) ^ (((off) >> 3) & 0x30))

__device__ __forceinline__ void cp16(uint32_t saddr, const void* g) {
    asm volatile("cp.async.cg.shared.global [%0], [%1], 16;" :: "r"(saddr), "l"(g));
}
#define CP_COMMIT() asm volatile("cp.async.commit_group;" ::: "memory")
#define CP_WAIT0()  asm volatile("cp.async.wait_group 0;" ::: "memory")
#define CP_WAIT1()  asm volatile("cp.async.wait_group 1;" ::: "memory")

__device__ __forceinline__ void ldm_x4(uint32_t* r, uint32_t addr) {
    asm volatile("ldmatrix.sync.aligned.m8n8.x4.shared.b16 {%0,%1,%2,%3}, [%4];"
                 : "=r"(r[0]), "=r"(r[1]), "=r"(r[2]), "=r"(r[3]) : "r"(addr));
}

__device__ __forceinline__ void mma_f16(float* d, const uint32_t* a, const uint32_t* b) {
    asm volatile("mma.sync.aligned.m16n8k16.row.col.f32.f16.f16.f32 "
                 "{%0,%1,%2,%3}, {%4,%5,%6,%7}, {%8,%9}, {%0,%1,%2,%3};"
                 : "+f"(d[0]), "+f"(d[1]), "+f"(d[2]), "+f"(d[3])
                 : "r"(a[0]), "r"(a[1]), "r"(a[2]), "r"(a[3]), "r"(b[0]), "r"(b[1]));
}

// ---------------------------------------------------------------------------
// split2: fp32 -> fp16 hi + fp16 lo (residual)
// ---------------------------------------------------------------------------
__global__ void __launch_bounds__(256)
split2_kernel(const float* __restrict__ in, __half* __restrict__ hi,
              __half* __restrict__ lo, int n4)
{
    int i = blockIdx.x * 256 + threadIdx.x;
    if (i >= n4) return;
    float4 v = ((const float4*)in)[i];
    __half h[4], l[4];
    float f[4] = {v.x, v.y, v.z, v.w};
#pragma unroll
    for (int j = 0; j < 4; j++) {
        h[j] = __float2half(f[j]);
        l[j] = __float2half(f[j] - __half2float(h[j]));
    }
    ((uint64_t*)hi)[i] = *(const uint64_t*)h;
    ((uint64_t*)lo)[i] = *(const uint64_t*)l;
}

// ---------------------------------------------------------------------------
// cvt: fp32 -> fp16
// ---------------------------------------------------------------------------
__global__ void __launch_bounds__(256)
cvt_kernel(const float* __restrict__ in, __half* __restrict__ out, int n4)
{
    int i = blockIdx.x * 256 + threadIdx.x;
    if (i >= n4) return;
    float4 v = ((const float4*)in)[i];
    __half h[4] = {__float2half(v.x), __float2half(v.y),
                   __float2half(v.z), __float2half(v.w)};
    ((uint64_t*)out)[i] = *(const uint64_t*)h;
}

// ---------------------------------------------------------------------------
// OPERAND-SWAPPED fp16 2-term GEMM: C[token][chan] = X(hi+lo) x W^T (+bias)
// A operand = W (single fp16, high reuse), B operand = X hi/lo.
// CTA tile: 128 chans x 128 tokens, BK=32 (64B rows, SW64), 8 warps (2x4),
// warp tile 64 chans x 32 tokens. 3-stage ring (72KB) -> 2 CTAs/SM.
// smem traffic: 16 ldm/chunk (vs 20 unswapped). Epilogue: smem transpose ->
// coalesced [token][chan] float4 stores.
// ---------------------------------------------------------------------------
#define GBK      32
#define SUB_B_HI 8192
#define SUB_B_LO 16384
#define STAGE_SZ 24576
#define NSTAGE   3
#define GSMEM_SZ (NSTAGE * STAGE_SZ)   // 73728 per CTA (also fits 128x132 fp32)

__device__ __forceinline__ void fill_chunk(
    int cc, uint32_t dst, int tid, int m0w, int n0t, int K,
    const __half* __restrict__ W,
    const __half* __restrict__ Xhi, const __half* __restrict__ Xlo)
{
    const int kk = cc * GBK;
#pragma unroll
    for (int i = 0; i < 2; i++) {
        const int u = tid + i * 256;             // 512 16B-units per sub-tile
        const int row = u >> 2, c16 = u & 3;     // 4 units per 64B row
        const uint32_t so = SWZ64((uint32_t)(row * 64 + c16 * 16));
        const size_t woff = (size_t)(m0w + row) * K + kk + c16 * 8;
        const size_t xoff = (size_t)(n0t + row) * K + kk + c16 * 8;
        cp16(dst + so,            W + woff);
        cp16(dst + SUB_B_HI + so, Xhi + xoff);
        cp16(dst + SUB_B_LO + so, Xlo + xoff);
    }
}

__global__ void __launch_bounds__(256, 2)
gemm_f16x2(const __half* __restrict__ W,
           const __half* __restrict__ Xhi, const __half* __restrict__ Xlo,
           float* __restrict__ C, const float* __restrict__ bias, int N, int K)
{
    extern __shared__ char smem[];
    const uint32_t sb = smem_u32(smem);
    const int tid = threadIdx.x;
    const int m0w = blockIdx.x * 128;   // output-channel tile (x-fastest: W stays L2-resident)
    const int n0t = blockIdx.y * 128;   // token tile
    const int lane = tid & 31;
    const int warp = tid >> 5;
    const int warp_m = warp >> 2;      // 0..1 (64 chans each)
    const int warp_n = warp & 3;       // 0..3 (32 tokens each)

    float acc[4][4][4];
#pragma unroll
    for (int a = 0; a < 4; a++)
#pragma unroll
        for (int b = 0; b < 4; b++)
#pragma unroll
            for (int c = 0; c < 4; c++) acc[a][b][c] = 0.f;

    const int kchunks = K / GBK;       // 32

    fill_chunk(0, sb, tid, m0w, n0t, K, W, Xhi, Xlo);
    CP_COMMIT();
    fill_chunk(1, sb + STAGE_SZ, tid, m0w, n0t, K, W, Xhi, Xlo);
    CP_COMMIT();

    // ldmatrix per-thread address components (pre-swizzle byte offsets, 64B rows)
    const uint32_t a_row_half = (uint32_t)(lane & 15);
    const uint32_t a_koff     = (uint32_t)((lane >> 4) << 4);
    const uint32_t b_row_half = (uint32_t)(((lane >> 4) << 3) + (lane & 7));
    const uint32_t b_koff     = (uint32_t)(((lane >> 3) & 1) << 4);

    for (int cc = 0; cc < kchunks; cc++) {
        if (cc + 1 < kchunks) { CP_WAIT1(); } else { CP_WAIT0(); }
        __syncthreads();
        if (cc + 2 < kchunks) {
            fill_chunk(cc + 2, sb + (uint32_t)((cc + 2) % NSTAGE) * STAGE_SZ,
                       tid, m0w, n0t, K, W, Xhi, Xlo);
            CP_COMMIT();
        }
        const uint32_t st = sb + (uint32_t)(cc % NSTAGE) * STAGE_SZ;

#pragma unroll
        for (int ks = 0; ks < 2; ks++) {
            uint32_t bh[2][4], bl[2][4];
#pragma unroll
            for (int nt2 = 0; nt2 < 2; nt2++) {
                const uint32_t row = (uint32_t)(warp_n * 32 + nt2 * 16) + b_row_half;
                const uint32_t so = SWZ64(row * 64 + (uint32_t)(ks * 32) + b_koff);
                ldm_x4(bh[nt2], st + SUB_B_HI + so);
                ldm_x4(bl[nt2], st + SUB_B_LO + so);
            }
#pragma unroll
            for (int mt = 0; mt < 4; mt++) {
                uint32_t aw[4];
                const uint32_t row = (uint32_t)(warp_m * 64 + mt * 16) + a_row_half;
                const uint32_t so = SWZ64(row * 64 + (uint32_t)(ks * 32) + a_koff);
                ldm_x4(aw, st + so);
#pragma unroll
                for (int nt = 0; nt < 4; nt++) {
                    const uint32_t* bph = &bh[nt >> 1][(nt & 1) * 2];
                    const uint32_t* bpl = &bl[nt >> 1][(nt & 1) * 2];
                    mma_f16(acc[mt][nt], aw, bph);
                    mma_f16(acc[mt][nt], aw, bpl);
                }
            }
        }
    }

    __syncthreads();

    // ---- epilogue: transpose through smem, coalesced [token][chan] writes ----
    float* smT = (float*)smem;         // [128 tokens][132 floats] = 67584 B
    const int ln4 = lane >> 2;
    const int lc2 = (lane & 3) * 2;
#pragma unroll
    for (int mt = 0; mt < 4; mt++) {
        const int chan0 = warp_m * 64 + mt * 16 + ln4;
#pragma unroll
        for (int nt = 0; nt < 4; nt++) {
            const int tok0 = warp_n * 32 + nt * 8 + lc2;
            smT[tok0 * 132 + chan0]           = acc[mt][nt][0];
            smT[(tok0 + 1) * 132 + chan0]     = acc[mt][nt][1];
            smT[tok0 * 132 + chan0 + 8]       = acc[mt][nt][2];
            smT[(tok0 + 1) * 132 + chan0 + 8] = acc[mt][nt][3];
        }
    }
    __syncthreads();

    for (int u = tid; u < 128 * 32; u += 256) {
        const int tok = u >> 5;
        const int c4  = (u & 31) * 4;
        float4 v = *(float4*)&smT[tok * 132 + c4];
        if (bias) {
            v.x += bias[m0w + c4 + 0];
            v.y += bias[m0w + c4 + 1];
            v.z += bias[m0w + c4 + 2];
            v.w += bias[m0w + c4 + 3];
        }
        *(float4*)(C + (size_t)(n0t + tok) * N + m0w + c4) = v;
    }
}

// ---------------------------------------------------------------------------
// Attention: one block per (sequence, head). Writes fp16 hi/lo split output.
// ---------------------------------------------------------------------------
__global__ void __launch_bounds__(256)
attn_kernel(const float* __restrict__ qkv,
            __half* __restrict__ att_hi, __half* __restrict__ att_lo)
{
    const int blk  = blockIdx.x;
    const int head = blk & 15;
    const int n    = blk >> 4;
    const int b    = n / HWP;
    const int hw   = n - b * HWP;
    const size_t base_tok = (size_t)b * (TT * HWP) + hw;

    __shared__ float Qs[32][65];
    __shared__ float Ks[32][65];
    __shared__ float Vs[32][64];
    __shared__ float Ss[32][33];

    const int tid = threadIdx.x;

    for (int i = tid; i < 32 * 64; i += 256) {
        const int t = i >> 6, d = i & 63;
        const size_t tok = base_tok + (size_t)t * HWP;
        const float* p = qkv + tok * EQKV + head * HD + d;
        Qs[t][d] = p[0];
        Ks[t][d] = p[1024];
        Vs[t][d] = p[2048];
    }
    __syncthreads();

    for (int i = tid; i < 2 * 32 * 16; i += 256) {
        const int mat = i >> 9;
        const int rem = i & 511;
        const int t = rem >> 4, j = rem & 15;
        const float freq = powf(10000.0f, -(float)j / 16.0f);
        const float ang = (float)t * freq;
        const float c = cosf(ang), s = sinf(ang);
        float (*P)[65] = mat ? Ks : Qs;
        const float x0 = P[t][2 * j];
        const float x1 = P[t][2 * j + 1];
        P[t][2 * j]     = x0 * c - x1 * s;
        P[t][2 * j + 1] = x1 * c + x0 * s;
    }
    __syncthreads();

    const int r = tid >> 4, c = tid & 15;
    {
        float s00 = 0.f, s01 = 0.f, s10 = 0.f, s11 = 0.f;
#pragma unroll 16
        for (int d = 0; d < 64; d++) {
            const float q0 = Qs[2 * r][d],     q1 = Qs[2 * r + 1][d];
            const float k0 = Ks[2 * c][d],     k1 = Ks[2 * c + 1][d];
            s00 += q0 * k0; s01 += q0 * k1;
            s10 += q1 * k0; s11 += q1 * k1;
        }
        Ss[2 * r][2 * c]         = s00;
        Ss[2 * r][2 * c + 1]     = s01;
        Ss[2 * r + 1][2 * c]     = s10;
        Ss[2 * r + 1][2 * c + 1] = s11;
    }
    __syncthreads();

    const int warp = tid >> 5, lane = tid & 31;
    const float scale = 0.125f;
#pragma unroll
    for (int qi = 0; qi < 4; qi++) {
        const int q = warp * 4 + qi;
        float s = (lane <= q) ? Ss[q][lane] * scale : -INFINITY;
        float m = s;
#pragma unroll
        for (int o = 16; o > 0; o >>= 1)
            m = fmaxf(m, __shfl_xor_sync(0xffffffffu, m, o));
        const float e = expf(s - m);
        float sum = e;
#pragma unroll
        for (int o = 16; o > 0; o >>= 1)
            sum += __shfl_xor_sync(0xffffffffu, sum, o);
        Ss[q][lane] = e / sum;
    }
    __syncthreads();

    float o0[4] = {0.f, 0.f, 0.f, 0.f};
    float o1[4] = {0.f, 0.f, 0.f, 0.f};
#pragma unroll 8
    for (int k = 0; k < 32; k++) {
        const float p0 = Ss[2 * r][k];
        const float p1 = Ss[2 * r + 1][k];
#pragma unroll
        for (int j = 0; j < 4; j++) {
            const float v = Vs[k][4 * c + j];
            o0[j] += p0 * v;
            o1[j] += p1 * v;
        }
    }
#pragma unroll
    for (int i = 0; i < 2; i++) {
        const int t = 2 * r + i;
        const size_t tok = base_tok + (size_t)t * HWP;
        const size_t base = tok * EO + head * HD + 4 * c;
        const float* src = i ? o1 : o0;
        __half h[4], l[4];
#pragma unroll
        for (int j = 0; j < 4; j++) {
            h[j] = __float2half(src[j]);
            l[j] = __float2half(src[j] - __half2float(h[j]));
        }
        *(uint64_t*)(att_hi + base) = *(const uint64_t*)h;
        *(uint64_t*)(att_lo + base) = *(const uint64_t*)l;
    }
}

// ---------------------------------------------------------------------------
extern "C" void kernel_launch(void* const* d_in, const int* in_sizes, int n_in,
                              void* d_out, int out_size)
{
    const float* x     = (const float*)d_in[0];
    const float* w_qkv = (const float*)d_in[1];
    const float* w_out = (const float*)d_in[2];
    const float* b_out = (const float*)d_in[3];
    float* out = (float*)d_out;

    void *qkv_p, *xh_p, *xl_p, *wq_p, *wo_p, *ah_p, *al_p;
    cudaGetSymbolAddress(&qkv_p, g_qkv);
    cudaGetSymbolAddress(&xh_p,  g_x_hi);   cudaGetSymbolAddress(&xl_p,  g_x_lo);
    cudaGetSymbolAddress(&wq_p,  g_wq);     cudaGetSymbolAddress(&wo_p,  g_wo);
    cudaGetSymbolAddress(&ah_p,  g_att_hi); cudaGetSymbolAddress(&al_p,  g_att_lo);

    float* qkv = (float*)qkv_p;
    __half *xh = (__half*)xh_p, *xl = (__half*)xl_p;
    __half *wq = (__half*)wq_p, *wo = (__half*)wo_p;
    __half *ah = (__half*)ah_p, *al = (__half*)al_p;

    cudaFuncSetAttribute(gemm_f16x2, cudaFuncAttributeMaxDynamicSharedMemorySize, GSMEM_SZ);

    // 0) split x into fp16 hi/lo; convert weights to fp16
    {
        int n4 = (MTOK * DIM) / 4;
        split2_kernel<<<(n4 + 255) / 256, 256>>>(x, xh, xl, n4);
        n4 = (EQKV * DIM) / 4;
        cvt_kernel<<<(n4 + 255) / 256, 256>>>(w_qkv, wq, n4);
        n4 = (DIM * DIM) / 4;
        cvt_kernel<<<(n4 + 255) / 256, 256>>>(w_out, wo, n4);
    }
    // 1) QKV projection: qkv[token][3072] = x x w_qkv^T
    {
        dim3 grid(EQKV / 128, MTOK / 128);   // x = chan tiles (W L2-resident), y = token tiles
        gemm_f16x2<<<grid, 256, GSMEM_SZ>>>(wq, xh, xl, qkv, nullptr, EQKV, DIM);
    }
    // 2) RoPE + causal attention, writes split fp16 att
    {
        attn_kernel<<<(BB * HWP) * HEADS, 256>>>(qkv, ah, al);
    }
    // 3) Output projection + bias: out[token][1024] = att x w_out^T + b
    {
        dim3 grid(DIM / 128, MTOK / 128);
        gemm_f16x2<<<grid, 256, GSMEM_SZ>>>(wo, ah, al, out, b_out, DIM, DIM);
    }
}

// round 14
// speedup vs baseline: 1.3367x; 1.3367x over previous
#include <cuda_runtime.h>
#include <cuda_fp16.h>
#include <cstdint>
#include <math.h>

// Problem constants
#define BB    2
#define TT    32
#define HH    18
#define WW    32
#define DIM   1024
#define HEADS 16
#define HD    64
#define HWP   (HH*WW)            // 576
#define MTOK  (BB*TT*HWP)        // 36864 tokens
#define EQKV  (3*HEADS*HD)       // 3072
#define EO    (HEADS*HD)         // 1024

// ---------------- scratch (device globals; no allocation allowed) ----------
__device__ float   g_qkv[(size_t)MTOK * EQKV];
__device__ __half  g_x16[(size_t)MTOK * DIM];
__device__ __half  g_wq[(size_t)EQKV * DIM];
__device__ __half  g_wo[(size_t)DIM * DIM];
__device__ __half  g_att_hi[(size_t)MTOK * EO];
__device__ __half  g_att_lo[(size_t)MTOK * EO];

// ---------------- helpers ---------------------------------------------------
__device__ __forceinline__ uint32_t smem_u32(const void* p) {
    uint32_t a;
    asm("{ .reg .u64 t; cvta.to.shared.u64 t, %1; cvt.u32.u64 %0, t; }" : "=r"(a) : "l"(p));
    return a;
}

// SW64 swizzle: 64-byte rows, 8-row/512B atom
#define SWZ64(off) ((off) ^ (((off) >> 3) & 0x30))

__device__ __forceinline__ void cp16(uint32_t saddr, const void* g) {
    asm volatile("cp.async.cg.shared.global [%0], [%1], 16;" :: "r"(saddr), "l"(g));
}
#define CP_COMMIT() asm volatile("cp.async.commit_group;" ::: "memory")
#define CP_WAIT0()  asm volatile("cp.async.wait_group 0;" ::: "memory")
#define CP_WAIT1()  asm volatile("cp.async.wait_group 1;" ::: "memory")

__device__ __forceinline__ void ldm_x4(uint32_t* r, uint32_t addr) {
    asm volatile("ldmatrix.sync.aligned.m8n8.x4.shared.b16 {%0,%1,%2,%3}, [%4];"
                 : "=r"(r[0]), "=r"(r[1]), "=r"(r[2]), "=r"(r[3]) : "r"(addr));
}

__device__ __forceinline__ void mma_f16(float* d, const uint32_t* a, const uint32_t* b) {
    asm volatile("mma.sync.aligned.m16n8k16.row.col.f32.f16.f16.f32 "
                 "{%0,%1,%2,%3}, {%4,%5,%6,%7}, {%8,%9}, {%0,%1,%2,%3};"
                 : "+f"(d[0]), "+f"(d[1]), "+f"(d[2]), "+f"(d[3])
                 : "r"(a[0]), "r"(a[1]), "r"(a[2]), "r"(a[3]), "r"(b[0]), "r"(b[1]));
}

// ---------------------------------------------------------------------------
// split2: fp32 -> fp16 hi + fp16 lo (residual)
// ---------------------------------------------------------------------------
__global__ void __launch_bounds__(256)
split2_kernel(const float* __restrict__ in, __half* __restrict__ hi,
              __half* __restrict__ lo, int n4)
{
    int i = blockIdx.x * 256 + threadIdx.x;
    if (i >= n4) return;
    float4 v = ((const float4*)in)[i];
    __half h[4], l[4];
    float f[4] = {v.x, v.y, v.z, v.w};
#pragma unroll
    for (int j = 0; j < 4; j++) {
        h[j] = __float2half(f[j]);
        l[j] = __float2half(f[j] - __half2float(h[j]));
    }
    ((uint64_t*)hi)[i] = *(const uint64_t*)h;
    ((uint64_t*)lo)[i] = *(const uint64_t*)l;
}

// ---------------------------------------------------------------------------
// cvt: fp32 -> fp16
// ---------------------------------------------------------------------------
__global__ void __launch_bounds__(256)
cvt_kernel(const float* __restrict__ in, __half* __restrict__ out, int n4)
{
    int i = blockIdx.x * 256 + threadIdx.x;
    if (i >= n4) return;
    float4 v = ((const float4*)in)[i];
    __half h[4] = {__float2half(v.x), __float2half(v.y),
                   __float2half(v.z), __float2half(v.w)};
    ((uint64_t*)out)[i] = *(const uint64_t*)h;
}

// ---------------------------------------------------------------------------
// OPERAND-SWAPPED fp16 GEMM (1- or 2-term): C[token][chan] = X x W^T (+bias)
// A operand = W (single fp16), B operand = X (hi [+ lo if HASLO]).
// CTA tile: 128 chans x 128 tokens, BK=32 (64B rows, SW64), 8 warps (2x4),
// warp tile 64 chans x 32 tokens. 3-stage ring -> 2 CTAs/SM.
// 2-term path is term-outer/nt-inner: same-acc mma dependency distance = 4.
// Epilogue: smem transpose -> coalesced [token][chan] float4 stores.
// ---------------------------------------------------------------------------
#define GBK      32
#define SUB_B_HI 8192
#define SUB_B_LO 16384
#define STAGE_SZ 24576
#define NSTAGE   3
#define GSMEM_SZ (NSTAGE * STAGE_SZ)   // 73728 per CTA (also fits 128x132 fp32)

template <bool HASLO>
__device__ __forceinline__ void fill_chunk(
    int cc, uint32_t dst, int tid, int m0w, int n0t, int K,
    const __half* __restrict__ W,
    const __half* __restrict__ Xhi, const __half* __restrict__ Xlo)
{
    const int kk = cc * GBK;
#pragma unroll
    for (int i = 0; i < 2; i++) {
        const int u = tid + i * 256;             // 512 16B-units per sub-tile
        const int row = u >> 2, c16 = u & 3;     // 4 units per 64B row
        const uint32_t so = SWZ64((uint32_t)(row * 64 + c16 * 16));
        const size_t woff = (size_t)(m0w + row) * K + kk + c16 * 8;
        const size_t xoff = (size_t)(n0t + row) * K + kk + c16 * 8;
        cp16(dst + so,            W + woff);
        cp16(dst + SUB_B_HI + so, Xhi + xoff);
        if (HASLO) cp16(dst + SUB_B_LO + so, Xlo + xoff);
    }
}

template <bool HASLO>
__global__ void __launch_bounds__(256, 2)
gemm_f16(const __half* __restrict__ W,
         const __half* __restrict__ Xhi, const __half* __restrict__ Xlo,
         float* __restrict__ C, const float* __restrict__ bias, int N, int K)
{
    extern __shared__ char smem[];
    const uint32_t sb = smem_u32(smem);
    const int tid = threadIdx.x;
    const int m0w = blockIdx.x * 128;   // output-channel tile (x-fastest: W stays L2-resident)
    const int n0t = blockIdx.y * 128;   // token tile
    const int lane = tid & 31;
    const int warp = tid >> 5;
    const int warp_m = warp >> 2;      // 0..1 (64 chans each)
    const int warp_n = warp & 3;       // 0..3 (32 tokens each)

    float acc[4][4][4];
#pragma unroll
    for (int a = 0; a < 4; a++)
#pragma unroll
        for (int b = 0; b < 4; b++)
#pragma unroll
            for (int c = 0; c < 4; c++) acc[a][b][c] = 0.f;

    const int kchunks = K / GBK;       // 32

    fill_chunk<HASLO>(0, sb, tid, m0w, n0t, K, W, Xhi, Xlo);
    CP_COMMIT();
    fill_chunk<HASLO>(1, sb + STAGE_SZ, tid, m0w, n0t, K, W, Xhi, Xlo);
    CP_COMMIT();

    // ldmatrix per-thread address components (pre-swizzle byte offsets, 64B rows)
    const uint32_t a_row_half = (uint32_t)(lane & 15);
    const uint32_t a_koff     = (uint32_t)((lane >> 4) << 4);
    const uint32_t b_row_half = (uint32_t)(((lane >> 4) << 3) + (lane & 7));
    const uint32_t b_koff     = (uint32_t)(((lane >> 3) & 1) << 4);

    for (int cc = 0; cc < kchunks; cc++) {
        if (cc + 1 < kchunks) { CP_WAIT1(); } else { CP_WAIT0(); }
        __syncthreads();
        if (cc + 2 < kchunks) {
            fill_chunk<HASLO>(cc + 2, sb + (uint32_t)((cc + 2) % NSTAGE) * STAGE_SZ,
                              tid, m0w, n0t, K, W, Xhi, Xlo);
            CP_COMMIT();
        }
        const uint32_t st = sb + (uint32_t)(cc % NSTAGE) * STAGE_SZ;

#pragma unroll
        for (int ks = 0; ks < 2; ks++) {
            uint32_t bh[2][4], bl[2][4];
#pragma unroll
            for (int nt2 = 0; nt2 < 2; nt2++) {
                const uint32_t row = (uint32_t)(warp_n * 32 + nt2 * 16) + b_row_half;
                const uint32_t so = SWZ64(row * 64 + (uint32_t)(ks * 32) + b_koff);
                ldm_x4(bh[nt2], st + SUB_B_HI + so);
                if (HASLO) ldm_x4(bl[nt2], st + SUB_B_LO + so);
            }
#pragma unroll
            for (int mt = 0; mt < 4; mt++) {
                uint32_t aw[4];
                const uint32_t row = (uint32_t)(warp_m * 64 + mt * 16) + a_row_half;
                const uint32_t so = SWZ64(row * 64 + (uint32_t)(ks * 32) + a_koff);
                ldm_x4(aw, st + so);
                // term-outer ordering: same-acc dependency distance = 4
#pragma unroll
                for (int nt = 0; nt < 4; nt++)
                    mma_f16(acc[mt][nt], aw, &bh[nt >> 1][(nt & 1) * 2]);
                if (HASLO) {
#pragma unroll
                    for (int nt = 0; nt < 4; nt++)
                        mma_f16(acc[mt][nt], aw, &bl[nt >> 1][(nt & 1) * 2]);
                }
            }
        }
    }

    __syncthreads();

    // ---- epilogue: transpose through smem, coalesced [token][chan] writes ----
    float* smT = (float*)smem;         // [128 tokens][132 floats] = 67584 B
    const int ln4 = lane >> 2;
    const int lc2 = (lane & 3) * 2;
#pragma unroll
    for (int mt = 0; mt < 4; mt++) {
        const int chan0 = warp_m * 64 + mt * 16 + ln4;
#pragma unroll
        for (int nt = 0; nt < 4; nt++) {
            const int tok0 = warp_n * 32 + nt * 8 + lc2;
            smT[tok0 * 132 + chan0]           = acc[mt][nt][0];
            smT[(tok0 + 1) * 132 + chan0]     = acc[mt][nt][1];
            smT[tok0 * 132 + chan0 + 8]       = acc[mt][nt][2];
            smT[(tok0 + 1) * 132 + chan0 + 8] = acc[mt][nt][3];
        }
    }
    __syncthreads();

    for (int u = tid; u < 128 * 32; u += 256) {
        const int tok = u >> 5;
        const int c4  = (u & 31) * 4;
        float4 v = *(float4*)&smT[tok * 132 + c4];
        if (bias) {
            v.x += bias[m0w + c4 + 0];
            v.y += bias[m0w + c4 + 1];
            v.z += bias[m0w + c4 + 2];
            v.w += bias[m0w + c4 + 3];
        }
        *(float4*)(C + (size_t)(n0t + tok) * N + m0w + c4) = v;
    }
}

// ---------------------------------------------------------------------------
// Attention: one block per (sequence, head). Writes fp16 hi/lo split output.
// ---------------------------------------------------------------------------
__global__ void __launch_bounds__(256)
attn_kernel(const float* __restrict__ qkv,
            __half* __restrict__ att_hi, __half* __restrict__ att_lo)
{
    const int blk  = blockIdx.x;
    const int head = blk & 15;
    const int n    = blk >> 4;
    const int b    = n / HWP;
    const int hw   = n - b * HWP;
    const size_t base_tok = (size_t)b * (TT * HWP) + hw;

    __shared__ float Qs[32][65];
    __shared__ float Ks[32][65];
    __shared__ float Vs[32][64];
    __shared__ float Ss[32][33];

    const int tid = threadIdx.x;

    for (int i = tid; i < 32 * 64; i += 256) {
        const int t = i >> 6, d = i & 63;
        const size_t tok = base_tok + (size_t)t * HWP;
        const float* p = qkv + tok * EQKV + head * HD + d;
        Qs[t][d] = p[0];
        Ks[t][d] = p[1024];
        Vs[t][d] = p[2048];
    }
    __syncthreads();

    for (int i = tid; i < 2 * 32 * 16; i += 256) {
        const int mat = i >> 9;
        const int rem = i & 511;
        const int t = rem >> 4, j = rem & 15;
        const float freq = powf(10000.0f, -(float)j / 16.0f);
        const float ang = (float)t * freq;
        const float c = cosf(ang), s = sinf(ang);
        float (*P)[65] = mat ? Ks : Qs;
        const float x0 = P[t][2 * j];
        const float x1 = P[t][2 * j + 1];
        P[t][2 * j]     = x0 * c - x1 * s;
        P[t][2 * j + 1] = x1 * c + x0 * s;
    }
    __syncthreads();

    const int r = tid >> 4, c = tid & 15;
    {
        float s00 = 0.f, s01 = 0.f, s10 = 0.f, s11 = 0.f;
#pragma unroll 16
        for (int d = 0; d < 64; d++) {
            const float q0 = Qs[2 * r][d],     q1 = Qs[2 * r + 1][d];
            const float k0 = Ks[2 * c][d],     k1 = Ks[2 * c + 1][d];
            s00 += q0 * k0; s01 += q0 * k1;
            s10 += q1 * k0; s11 += q1 * k1;
        }
        Ss[2 * r][2 * c]         = s00;
        Ss[2 * r][2 * c + 1]     = s01;
        Ss[2 * r + 1][2 * c]     = s10;
        Ss[2 * r + 1][2 * c + 1] = s11;
    }
    __syncthreads();

    const int warp = tid >> 5, lane = tid & 31;
    const float scale = 0.125f;
#pragma unroll
    for (int qi = 0; qi < 4; qi++) {
        const int q = warp * 4 + qi;
        float s = (lane <= q) ? Ss[q][lane] * scale : -INFINITY;
        float m = s;
#pragma unroll
        for (int o = 16; o > 0; o >>= 1)
            m = fmaxf(m, __shfl_xor_sync(0xffffffffu, m, o));
        const float e = expf(s - m);
        float sum = e;
#pragma unroll
        for (int o = 16; o > 0; o >>= 1)
            sum += __shfl_xor_sync(0xffffffffu, sum, o);
        Ss[q][lane] = e / sum;
    }
    __syncthreads();

    float o0[4] = {0.f, 0.f, 0.f, 0.f};
    float o1[4] = {0.f, 0.f, 0.f, 0.f};
#pragma unroll 8
    for (int k = 0; k < 32; k++) {
        const float p0 = Ss[2 * r][k];
        const float p1 = Ss[2 * r + 1][k];
#pragma unroll
        for (int j = 0; j < 4; j++) {
            const float v = Vs[k][4 * c + j];
            o0[j] += p0 * v;
            o1[j] += p1 * v;
        }
    }
#pragma unroll
    for (int i = 0; i < 2; i++) {
        const int t = 2 * r + i;
        const size_t tok = base_tok + (size_t)t * HWP;
        const size_t base = tok * EO + head * HD + 4 * c;
        const float* src = i ? o1 : o0;
        __half h[4], l[4];
#pragma unroll
        for (int j = 0; j < 4; j++) {
            h[j] = __float2half(src[j]);
            l[j] = __float2half(src[j] - __half2float(h[j]));
        }
        *(uint64_t*)(att_hi + base) = *(const uint64_t*)h;
        *(uint64_t*)(att_lo + base) = *(const uint64_t*)l;
    }
}

// ---------------------------------------------------------------------------
extern "C" void kernel_launch(void* const* d_in, const int* in_sizes, int n_in,
                              void* d_out, int out_size)
{
    const float* x     = (const float*)d_in[0];
    const float* w_qkv = (const float*)d_in[1];
    const float* w_out = (const float*)d_in[2];
    const float* b_out = (const float*)d_in[3];
    float* out = (float*)d_out;

    void *qkv_p, *x16_p, *wq_p, *wo_p, *ah_p, *al_p;
    cudaGetSymbolAddress(&qkv_p, g_qkv);
    cudaGetSymbolAddress(&x16_p, g_x16);
    cudaGetSymbolAddress(&wq_p,  g_wq);     cudaGetSymbolAddress(&wo_p,  g_wo);
    cudaGetSymbolAddress(&ah_p,  g_att_hi); cudaGetSymbolAddress(&al_p,  g_att_lo);

    float* qkv = (float*)qkv_p;
    __half *x16 = (__half*)x16_p;
    __half *wq = (__half*)wq_p, *wo = (__half*)wo_p;
    __half *ah = (__half*)ah_p, *al = (__half*)al_p;

    cudaFuncSetAttribute(gemm_f16<false>, cudaFuncAttributeMaxDynamicSharedMemorySize, GSMEM_SZ);
    cudaFuncSetAttribute(gemm_f16<true>,  cudaFuncAttributeMaxDynamicSharedMemorySize, GSMEM_SZ);

    // 0) convert x and weights to fp16
    {
        int n4 = (MTOK * DIM) / 4;
        cvt_kernel<<<(n4 + 255) / 256, 256>>>(x, x16, n4);
        n4 = (EQKV * DIM) / 4;
        cvt_kernel<<<(n4 + 255) / 256, 256>>>(w_qkv, wq, n4);
        n4 = (DIM * DIM) / 4;
        cvt_kernel<<<(n4 + 255) / 256, 256>>>(w_out, wo, n4);
    }
    // 1) QKV projection (1-term fp16): qkv[token][3072] = x x w_qkv^T
    {
        dim3 grid(EQKV / 128, MTOK / 128);   // x = chan tiles (W L2-resident), y = token tiles
        gemm_f16<false><<<grid, 256, GSMEM_SZ>>>(wq, x16, nullptr, qkv, nullptr, EQKV, DIM);
    }
    // 2) RoPE + causal attention, writes split fp16 att
    {
        attn_kernel<<<(BB * HWP) * HEADS, 256>>>(qkv, ah, al);
    }
    // 3) Output projection + bias (2-term): out[token][1024] = (att_hi+att_lo) x w_out^T + b
    {
        dim3 grid(DIM / 128, MTOK / 128);
        gemm_f16<true><<<grid, 256, GSMEM_SZ>>>(wo, ah, al, out, b_out, DIM, DIM);
    }
}

// round 15
// speedup vs baseline: 1.5548x; 1.1632x over previous
#include <cuda_runtime.h>
#include <cuda_fp16.h>
#include <cstdint>
#include <math.h>

// Problem constants
#define BB    2
#define TT    32
#define HH    18
#define WW    32
#define DIM   1024
#define HEADS 16
#define HD    64
#define HWP   (HH*WW)            // 576
#define MTOK  (BB*TT*HWP)        // 36864 tokens
#define EQKV  (3*HEADS*HD)       // 3072
#define EO    (HEADS*HD)         // 1024

// ---------------- scratch (device globals; no allocation allowed) ----------
__device__ __half  g_qkv[(size_t)MTOK * EQKV];     // fp16 qkv intermediate
__device__ __half  g_x16[(size_t)MTOK * DIM];
__device__ __half  g_wq[(size_t)EQKV * DIM];
__device__ __half  g_wo[(size_t)DIM * DIM];
__device__ __half  g_att[(size_t)MTOK * EO];       // fp16 attention out

// ---------------- helpers ---------------------------------------------------
__device__ __forceinline__ uint32_t smem_u32(const void* p) {
    uint32_t a;
    asm("{ .reg .u64 t; cvta.to.shared.u64 t, %1; cvt.u32.u64 %0, t; }" : "=r"(a) : "l"(p));
    return a;
}

// SW64 swizzle: 64-byte rows, 8-row/512B atom
#define SWZ64(off) ((off) ^ (((off) >> 3) & 0x30))

__device__ __forceinline__ void cp16(uint32_t saddr, const void* g) {
    asm volatile("cp.async.cg.shared.global [%0], [%1], 16;" :: "r"(saddr), "l"(g));
}
#define CP_COMMIT() asm volatile("cp.async.commit_group;" ::: "memory")
#define CP_WAIT2()  asm volatile("cp.async.wait_group 2;" ::: "memory")

__device__ __forceinline__ void ldm_x4(uint32_t* r, uint32_t addr) {
    asm volatile("ldmatrix.sync.aligned.m8n8.x4.shared.b16 {%0,%1,%2,%3}, [%4];"
                 : "=r"(r[0]), "=r"(r[1]), "=r"(r[2]), "=r"(r[3]) : "r"(addr));
}

__device__ __forceinline__ void mma_f16(float* d, const uint32_t* a, const uint32_t* b) {
    asm volatile("mma.sync.aligned.m16n8k16.row.col.f32.f16.f16.f32 "
                 "{%0,%1,%2,%3}, {%4,%5,%6,%7}, {%8,%9}, {%0,%1,%2,%3};"
                 : "+f"(d[0]), "+f"(d[1]), "+f"(d[2]), "+f"(d[3])
                 : "r"(a[0]), "r"(a[1]), "r"(a[2]), "r"(a[3]), "r"(b[0]), "r"(b[1]));
}

// ---------------------------------------------------------------------------
// cvt: fp32 -> fp16
// ---------------------------------------------------------------------------
__global__ void __launch_bounds__(256)
cvt_kernel(const float* __restrict__ in, __half* __restrict__ out, int n4)
{
    int i = blockIdx.x * 256 + threadIdx.x;
    if (i >= n4) return;
    float4 v = ((const float4*)in)[i];
    __half h[4] = {__float2half(v.x), __float2half(v.y),
                   __float2half(v.z), __float2half(v.w)};
    ((uint64_t*)out)[i] = *(const uint64_t*)h;
}

// ---------------------------------------------------------------------------
// OPERAND-SWAPPED fp16 1-term GEMM: C[token][chan] = X x W^T (+bias)
// A operand = W, B operand = X. CTA tile 128 chans x 128 tokens, BK=32
// (64B rows, SW64), 8 warps (2x4), warp tile 64 chans x 32 tokens.
// 4-stage cp.async ring (64KB), commit-per-iter + wait_group 2 -> 2 CTAs/SM.
// Epilogue: smem transpose -> coalesced [token][chan] stores (fp16 or fp32).
// ---------------------------------------------------------------------------
#define GBK      32
#define SUB_X    8192
#define STAGE_SZ 16384
#define NSTAGE   4
#define GSMEM_SZ 67584                 // max(4*16384, 128*132*4 transpose)

__device__ __forceinline__ void fill_chunk(
    int cc, uint32_t dst, int tid, int m0w, int n0t, int K,
    const __half* __restrict__ W, const __half* __restrict__ X)
{
    const int kk = cc * GBK;
#pragma unroll
    for (int i = 0; i < 2; i++) {
        const int u = tid + i * 256;             // 512 16B-units per sub-tile
        const int row = u >> 2, c16 = u & 3;     // 4 units per 64B row
        const uint32_t so = SWZ64((uint32_t)(row * 64 + c16 * 16));
        cp16(dst + so,         W + (size_t)(m0w + row) * K + kk + c16 * 8);
        cp16(dst + SUB_X + so, X + (size_t)(n0t + row) * K + kk + c16 * 8);
    }
}

template <bool OUT16>
__global__ void __launch_bounds__(256, 2)
gemm_f16(const __half* __restrict__ W, const __half* __restrict__ X,
         void* __restrict__ Cv, const float* __restrict__ bias, int N, int K)
{
    extern __shared__ char smem[];
    const uint32_t sb = smem_u32(smem);
    const int tid = threadIdx.x;
    const int m0w = blockIdx.x * 128;   // output-channel tile (x-fastest: W L2-resident)
    const int n0t = blockIdx.y * 128;   // token tile
    const int lane = tid & 31;
    const int warp = tid >> 5;
    const int warp_m = warp >> 2;      // 0..1 (64 chans each)
    const int warp_n = warp & 3;       // 0..3 (32 tokens each)

    float acc[4][4][4];
#pragma unroll
    for (int a = 0; a < 4; a++)
#pragma unroll
        for (int b = 0; b < 4; b++)
#pragma unroll
            for (int c = 0; c < 4; c++) acc[a][b][c] = 0.f;

    const int kchunks = K / GBK;       // 32

    // prologue: fill stages 0..2
#pragma unroll
    for (int p = 0; p < NSTAGE - 1; p++) {
        fill_chunk(p, sb + (uint32_t)p * STAGE_SZ, tid, m0w, n0t, K, W, X);
        CP_COMMIT();
    }

    // ldmatrix per-thread address components (pre-swizzle byte offsets, 64B rows)
    const uint32_t a_row_half = (uint32_t)(lane & 15);
    const uint32_t a_koff     = (uint32_t)((lane >> 4) << 4);
    const uint32_t b_row_half = (uint32_t)(((lane >> 4) << 3) + (lane & 7));
    const uint32_t b_koff     = (uint32_t)(((lane >> 3) & 1) << 4);

    for (int cc = 0; cc < kchunks; cc++) {
        CP_WAIT2();                    // commit-per-iter => chunks <= cc complete
        __syncthreads();
        if (cc + NSTAGE - 1 < kchunks)
            fill_chunk(cc + NSTAGE - 1,
                       sb + (uint32_t)((cc + NSTAGE - 1) % NSTAGE) * STAGE_SZ,
                       tid, m0w, n0t, K, W, X);
        CP_COMMIT();                   // may be empty; keeps group count in sync

        const uint32_t st = sb + (uint32_t)(cc % NSTAGE) * STAGE_SZ;

#pragma unroll
        for (int ks = 0; ks < 2; ks++) {
            uint32_t bx[2][4];
#pragma unroll
            for (int nt2 = 0; nt2 < 2; nt2++) {
                const uint32_t row = (uint32_t)(warp_n * 32 + nt2 * 16) + b_row_half;
                const uint32_t so = SWZ64(row * 64 + (uint32_t)(ks * 32) + b_koff);
                ldm_x4(bx[nt2], st + SUB_X + so);
            }
#pragma unroll
            for (int mt = 0; mt < 4; mt++) {
                uint32_t aw[4];
                const uint32_t row = (uint32_t)(warp_m * 64 + mt * 16) + a_row_half;
                const uint32_t so = SWZ64(row * 64 + (uint32_t)(ks * 32) + a_koff);
                ldm_x4(aw, st + so);
#pragma unroll
                for (int nt = 0; nt < 4; nt++)
                    mma_f16(acc[mt][nt], aw, &bx[nt >> 1][(nt & 1) * 2]);
            }
        }
    }

    __syncthreads();

    // ---- epilogue: transpose through smem, coalesced [token][chan] writes ----
    float* smT = (float*)smem;         // [128 tokens][132 floats] = 67584 B
    const int ln4 = lane >> 2;
    const int lc2 = (lane & 3) * 2;
#pragma unroll
    for (int mt = 0; mt < 4; mt++) {
        const int chan0 = warp_m * 64 + mt * 16 + ln4;
#pragma unroll
        for (int nt = 0; nt < 4; nt++) {
            const int tok0 = warp_n * 32 + nt * 8 + lc2;
            smT[tok0 * 132 + chan0]           = acc[mt][nt][0];
            smT[(tok0 + 1) * 132 + chan0]     = acc[mt][nt][1];
            smT[tok0 * 132 + chan0 + 8]       = acc[mt][nt][2];
            smT[(tok0 + 1) * 132 + chan0 + 8] = acc[mt][nt][3];
        }
    }
    __syncthreads();

    for (int u = tid; u < 128 * 32; u += 256) {
        const int tok = u >> 5;
        const int c4  = (u & 31) * 4;
        float4 v = *(float4*)&smT[tok * 132 + c4];
        if (bias) {
            v.x += bias[m0w + c4 + 0];
            v.y += bias[m0w + c4 + 1];
            v.z += bias[m0w + c4 + 2];
            v.w += bias[m0w + c4 + 3];
        }
        if (OUT16) {
            __half h[4] = {__float2half(v.x), __float2half(v.y),
                           __float2half(v.z), __float2half(v.w)};
            *(uint64_t*)((__half*)Cv + (size_t)(n0t + tok) * N + m0w + c4) =
                *(const uint64_t*)h;
        } else {
            *(float4*)((float*)Cv + (size_t)(n0t + tok) * N + m0w + c4) = v;
        }
    }
}

// ---------------------------------------------------------------------------
// Attention: one block per (sequence, head). fp16 qkv in, fp16 att out.
// All internal math fp32.
// ---------------------------------------------------------------------------
__global__ void __launch_bounds__(256)
attn_kernel(const __half* __restrict__ qkv, __half* __restrict__ att)
{
    const int blk  = blockIdx.x;
    const int head = blk & 15;
    const int n    = blk >> 4;
    const int b    = n / HWP;
    const int hw   = n - b * HWP;
    const size_t base_tok = (size_t)b * (TT * HWP) + hw;

    __shared__ float Qs[32][65];
    __shared__ float Ks[32][65];
    __shared__ float Vs[32][64];
    __shared__ float Ss[32][33];

    const int tid = threadIdx.x;

    for (int i = tid; i < 32 * 64; i += 256) {
        const int t = i >> 6, d = i & 63;
        const size_t tok = base_tok + (size_t)t * HWP;
        const __half* p = qkv + tok * EQKV + head * HD + d;
        Qs[t][d] = __half2float(p[0]);
        Ks[t][d] = __half2float(p[1024]);
        Vs[t][d] = __half2float(p[2048]);
    }
    __syncthreads();

    for (int i = tid; i < 2 * 32 * 16; i += 256) {
        const int mat = i >> 9;
        const int rem = i & 511;
        const int t = rem >> 4, j = rem & 15;
        const float freq = powf(10000.0f, -(float)j / 16.0f);
        const float ang = (float)t * freq;
        const float c = cosf(ang), s = sinf(ang);
        float (*P)[65] = mat ? Ks : Qs;
        const float x0 = P[t][2 * j];
        const float x1 = P[t][2 * j + 1];
        P[t][2 * j]     = x0 * c - x1 * s;
        P[t][2 * j + 1] = x1 * c + x0 * s;
    }
    __syncthreads();

    const int r = tid >> 4, c = tid & 15;
    {
        float s00 = 0.f, s01 = 0.f, s10 = 0.f, s11 = 0.f;
#pragma unroll 16
        for (int d = 0; d < 64; d++) {
            const float q0 = Qs[2 * r][d],     q1 = Qs[2 * r + 1][d];
            const float k0 = Ks[2 * c][d],     k1 = Ks[2 * c + 1][d];
            s00 += q0 * k0; s01 += q0 * k1;
            s10 += q1 * k0; s11 += q1 * k1;
        }
        Ss[2 * r][2 * c]         = s00;
        Ss[2 * r][2 * c + 1]     = s01;
        Ss[2 * r + 1][2 * c]     = s10;
        Ss[2 * r + 1][2 * c + 1] = s11;
    }
    __syncthreads();

    const int warp = tid >> 5, lane = tid & 31;
    const float scale = 0.125f;
#pragma unroll
    for (int qi = 0; qi < 4; qi++) {
        const int q = warp * 4 + qi;
        float s = (lane <= q) ? Ss[q][lane] * scale : -INFINITY;
        float m = s;
#pragma unroll
        for (int o = 16; o > 0; o >>= 1)
            m = fmaxf(m, __shfl_xor_sync(0xffffffffu, m, o));
        const float e = expf(s - m);
        float sum = e;
#pragma unroll
        for (int o = 16; o > 0; o >>= 1)
            sum += __shfl_xor_sync(0xffffffffu, sum, o);
        Ss[q][lane] = e / sum;
    }
    __syncthreads();

    float o0[4] = {0.f, 0.f, 0.f, 0.f};
    float o1[4] = {0.f, 0.f, 0.f, 0.f};
#pragma unroll 8
    for (int k = 0; k < 32; k++) {
        const float p0 = Ss[2 * r][k];
        const float p1 = Ss[2 * r + 1][k];
#pragma unroll
        for (int j = 0; j < 4; j++) {
            const float v = Vs[k][4 * c + j];
            o0[j] += p0 * v;
            o1[j] += p1 * v;
        }
    }
#pragma unroll
    for (int i = 0; i < 2; i++) {
        const int t = 2 * r + i;
        const size_t tok = base_tok + (size_t)t * HWP;
        const size_t base = tok * EO + head * HD + 4 * c;
        const float* src = i ? o1 : o0;
        __half h[4] = {__float2half(src[0]), __float2half(src[1]),
                       __float2half(src[2]), __float2half(src[3])};
        *(uint64_t*)(att + base) = *(const uint64_t*)h;
    }
}

// ---------------------------------------------------------------------------
extern "C" void kernel_launch(void* const* d_in, const int* in_sizes, int n_in,
                              void* d_out, int out_size)
{
    const float* x     = (const float*)d_in[0];
    const float* w_qkv = (const float*)d_in[1];
    const float* w_out = (const float*)d_in[2];
    const float* b_out = (const float*)d_in[3];
    float* out = (float*)d_out;

    void *qkv_p, *x16_p, *wq_p, *wo_p, *att_p;
    cudaGetSymbolAddress(&qkv_p, g_qkv);
    cudaGetSymbolAddress(&x16_p, g_x16);
    cudaGetSymbolAddress(&wq_p,  g_wq);
    cudaGetSymbolAddress(&wo_p,  g_wo);
    cudaGetSymbolAddress(&att_p, g_att);

    __half *qkv = (__half*)qkv_p;
    __half *x16 = (__half*)x16_p;
    __half *wq = (__half*)wq_p, *wo = (__half*)wo_p;
    __half *att = (__half*)att_p;

    cudaFuncSetAttribute(gemm_f16<true>,  cudaFuncAttributeMaxDynamicSharedMemorySize, GSMEM_SZ);
    cudaFuncSetAttribute(gemm_f16<false>, cudaFuncAttributeMaxDynamicSharedMemorySize, GSMEM_SZ);

    // 0) convert x and weights to fp16
    {
        int n4 = (MTOK * DIM) / 4;
        cvt_kernel<<<(n4 + 255) / 256, 256>>>(x, x16, n4);
        n4 = (EQKV * DIM) / 4;
        cvt_kernel<<<(n4 + 255) / 256, 256>>>(w_qkv, wq, n4);
        n4 = (DIM * DIM) / 4;
        cvt_kernel<<<(n4 + 255) / 256, 256>>>(w_out, wo, n4);
    }
    // 1) QKV projection (1-term fp16, fp16 out): qkv[token][3072] = x x w_qkv^T
    {
        dim3 grid(EQKV / 128, MTOK / 128);   // x = chan tiles (W L2-resident), y = token tiles
        gemm_f16<true><<<grid, 256, GSMEM_SZ>>>(wq, x16, qkv, nullptr, EQKV, DIM);
    }
    // 2) RoPE + causal attention (fp16 in/out, fp32 math)
    {
        attn_kernel<<<(BB * HWP) * HEADS, 256>>>(qkv, att);
    }
    // 3) Output projection + bias (1-term, fp32 out): out = att x w_out^T + b
    {
        dim3 grid(DIM / 128, MTOK / 128);
        gemm_f16<false><<<grid, 256, GSMEM_SZ>>>(wo, att, out, b_out, DIM, DIM);
    }
}

// round 16
// speedup vs baseline: 1.5826x; 1.0178x over previous
#include <cuda_runtime.h>
#include <cuda_fp16.h>
#include <cstdint>
#include <math.h>

// Problem constants
#define BB    2
#define TT    32
#define HH    18
#define WW    32
#define DIM   1024
#define HEADS 16
#define HD    64
#define HWP   (HH*WW)            // 576
#define MTOK  (BB*TT*HWP)        // 36864 tokens
#define EQKV  (3*HEADS*HD)       // 3072
#define EO    (HEADS*HD)         // 1024

// ---------------- scratch (device globals; no allocation allowed) ----------
__device__ __half  g_qkv[(size_t)MTOK * EQKV];     // fp16 qkv intermediate
__device__ __half  g_x16[(size_t)MTOK * DIM];
__device__ __half  g_wq[(size_t)EQKV * DIM];
__device__ __half  g_wo[(size_t)DIM * DIM];
__device__ __half  g_att[(size_t)MTOK * EO];       // fp16 attention out

// ---------------- helpers ---------------------------------------------------
__device__ __forceinline__ uint32_t smem_u32(const void* p) {
    uint32_t a;
    asm("{ .reg .u64 t; cvta.to.shared.u64 t, %1; cvt.u32.u64 %0, t; }" : "=r"(a) : "l"(p));
    return a;
}

// SW128 swizzle: 128-byte rows, 8-row/1KB atom
#define SWZ128(off) ((off) ^ (((off) >> 3) & 0x70))

__device__ __forceinline__ void cp16(uint32_t saddr, const void* g) {
    asm volatile("cp.async.cg.shared.global [%0], [%1], 16;" :: "r"(saddr), "l"(g));
}
#define CP_COMMIT() asm volatile("cp.async.commit_group;" ::: "memory")
#define CP_WAIT0()  asm volatile("cp.async.wait_group 0;" ::: "memory")
#define CP_WAIT1()  asm volatile("cp.async.wait_group 1;" ::: "memory")

__device__ __forceinline__ void ldm_x4(uint32_t* r, uint32_t addr) {
    asm volatile("ldmatrix.sync.aligned.m8n8.x4.shared.b16 {%0,%1,%2,%3}, [%4];"
                 : "=r"(r[0]), "=r"(r[1]), "=r"(r[2]), "=r"(r[3]) : "r"(addr));
}

__device__ __forceinline__ void mma_f16(float* d, const uint32_t* a, const uint32_t* b) {
    asm volatile("mma.sync.aligned.m16n8k16.row.col.f32.f16.f16.f32 "
                 "{%0,%1,%2,%3}, {%4,%5,%6,%7}, {%8,%9}, {%0,%1,%2,%3};"
                 : "+f"(d[0]), "+f"(d[1]), "+f"(d[2]), "+f"(d[3])
                 : "r"(a[0]), "r"(a[1]), "r"(a[2]), "r"(a[3]), "r"(b[0]), "r"(b[1]));
}

// ---------------------------------------------------------------------------
// cvt: fp32 -> fp16
// ---------------------------------------------------------------------------
__global__ void __launch_bounds__(256)
cvt_kernel(const float* __restrict__ in, __half* __restrict__ out, int n4)
{
    int i = blockIdx.x * 256 + threadIdx.x;
    if (i >= n4) return;
    float4 v = ((const float4*)in)[i];
    __half h[4] = {__float2half(v.x), __float2half(v.y),
                   __float2half(v.z), __float2half(v.w)};
    ((uint64_t*)out)[i] = *(const uint64_t*)h;
}

// ---------------------------------------------------------------------------
// OPERAND-SWAPPED fp16 1-term GEMM: C[token][chan] = X x W^T (+bias)
// A operand = W, B operand = X. CTA tile 128 chans x 128 tokens, BK=64
// (128B rows, SW128), 8 warps (2x4), warp tile 64 chans x 32 tokens.
// 64 mmas/warp between barriers (half the sync frequency of BK=32).
// 3-stage ring (96KB) -> 2 CTAs/SM. Epilogue: smem transpose ->
// coalesced [token][chan] stores (fp16 or fp32).
// ---------------------------------------------------------------------------
#define GBK      64
#define SUB_X    16384
#define STAGE_SZ 32768
#define NSTAGE   3
#define GSMEM_SZ (NSTAGE * STAGE_SZ)   // 98304 (transpose 67584 fits inside)

__device__ __forceinline__ void fill_chunk(
    int cc, uint32_t dst, int tid, int m0w, int n0t, int K,
    const __half* __restrict__ W, const __half* __restrict__ X)
{
    const int kk = cc * GBK;
#pragma unroll
    for (int i = 0; i < 4; i++) {
        const int u = tid + i * 256;             // 1024 16B-units per sub-tile
        const int row = u >> 3, c16 = u & 7;     // 8 units per 128B row
        const uint32_t so = SWZ128((uint32_t)(row * 128 + c16 * 16));
        cp16(dst + so,         W + (size_t)(m0w + row) * K + kk + c16 * 8);
        cp16(dst + SUB_X + so, X + (size_t)(n0t + row) * K + kk + c16 * 8);
    }
}

template <bool OUT16>
__global__ void __launch_bounds__(256, 2)
gemm_f16(const __half* __restrict__ W, const __half* __restrict__ X,
         void* __restrict__ Cv, const float* __restrict__ bias, int N, int K)
{
    extern __shared__ char smem[];
    const uint32_t sb = smem_u32(smem);
    const int tid = threadIdx.x;
    const int m0w = blockIdx.x * 128;   // output-channel tile (x-fastest: W L2-resident)
    const int n0t = blockIdx.y * 128;   // token tile
    const int lane = tid & 31;
    const int warp = tid >> 5;
    const int warp_m = warp >> 2;      // 0..1 (64 chans each)
    const int warp_n = warp & 3;       // 0..3 (32 tokens each)

    float acc[4][4][4];
#pragma unroll
    for (int a = 0; a < 4; a++)
#pragma unroll
        for (int b = 0; b < 4; b++)
#pragma unroll
            for (int c = 0; c < 4; c++) acc[a][b][c] = 0.f;

    const int kchunks = K / GBK;       // 16

    fill_chunk(0, sb, tid, m0w, n0t, K, W, X);
    CP_COMMIT();
    fill_chunk(1, sb + STAGE_SZ, tid, m0w, n0t, K, W, X);
    CP_COMMIT();

    // ldmatrix per-thread address components (pre-swizzle byte offsets, 128B rows)
    const uint32_t a_row_half = (uint32_t)(lane & 15);
    const uint32_t a_koff     = (uint32_t)((lane >> 4) << 4);
    const uint32_t b_row_half = (uint32_t)(((lane >> 4) << 3) + (lane & 7));
    const uint32_t b_koff     = (uint32_t)(((lane >> 3) & 1) << 4);

    for (int cc = 0; cc < kchunks; cc++) {
        if (cc + 1 < kchunks) { CP_WAIT1(); } else { CP_WAIT0(); }
        __syncthreads();
        if (cc + 2 < kchunks) {
            fill_chunk(cc + 2, sb + (uint32_t)((cc + 2) % NSTAGE) * STAGE_SZ,
                       tid, m0w, n0t, K, W, X);
            CP_COMMIT();
        }
        const uint32_t st = sb + (uint32_t)(cc % NSTAGE) * STAGE_SZ;

#pragma unroll
        for (int ks = 0; ks < 4; ks++) {
            const uint32_t kbyte = (uint32_t)(ks * 32);
            uint32_t bx[2][4];
#pragma unroll
            for (int nt2 = 0; nt2 < 2; nt2++) {
                const uint32_t row = (uint32_t)(warp_n * 32 + nt2 * 16) + b_row_half;
                const uint32_t so = SWZ128(row * 128 + kbyte + b_koff);
                ldm_x4(bx[nt2], st + SUB_X + so);
            }
#pragma unroll
            for (int mt = 0; mt < 4; mt++) {
                uint32_t aw[4];
                const uint32_t row = (uint32_t)(warp_m * 64 + mt * 16) + a_row_half;
                const uint32_t so = SWZ128(row * 128 + kbyte + a_koff);
                ldm_x4(aw, st + so);
#pragma unroll
                for (int nt = 0; nt < 4; nt++)
                    mma_f16(acc[mt][nt], aw, &bx[nt >> 1][(nt & 1) * 2]);
            }
        }
    }

    __syncthreads();

    // ---- epilogue: transpose through smem, coalesced [token][chan] writes ----
    float* smT = (float*)smem;         // [128 tokens][132 floats] = 67584 B
    const int ln4 = lane >> 2;
    const int lc2 = (lane & 3) * 2;
#pragma unroll
    for (int mt = 0; mt < 4; mt++) {
        const int chan0 = warp_m * 64 + mt * 16 + ln4;
#pragma unroll
        for (int nt = 0; nt < 4; nt++) {
            const int tok0 = warp_n * 32 + nt * 8 + lc2;
            smT[tok0 * 132 + chan0]           = acc[mt][nt][0];
            smT[(tok0 + 1) * 132 + chan0]     = acc[mt][nt][1];
            smT[tok0 * 132 + chan0 + 8]       = acc[mt][nt][2];
            smT[(tok0 + 1) * 132 + chan0 + 8] = acc[mt][nt][3];
        }
    }
    __syncthreads();

    for (int u = tid; u < 128 * 32; u += 256) {
        const int tok = u >> 5;
        const int c4  = (u & 31) * 4;
        float4 v = *(float4*)&smT[tok * 132 + c4];
        if (bias) {
            v.x += bias[m0w + c4 + 0];
            v.y += bias[m0w + c4 + 1];
            v.z += bias[m0w + c4 + 2];
            v.w += bias[m0w + c4 + 3];
        }
        if (OUT16) {
            __half h[4] = {__float2half(v.x), __float2half(v.y),
                           __float2half(v.z), __float2half(v.w)};
            *(uint64_t*)((__half*)Cv + (size_t)(n0t + tok) * N + m0w + c4) =
                *(const uint64_t*)h;
        } else {
            *(float4*)((float*)Cv + (size_t)(n0t + tok) * N + m0w + c4) = v;
        }
    }
}

// ---------------------------------------------------------------------------
// Attention: one block per (sequence, head). fp16 qkv in, fp16 att out.
// All internal math fp32.
// ---------------------------------------------------------------------------
__global__ void __launch_bounds__(256)
attn_kernel(const __half* __restrict__ qkv, __half* __restrict__ att)
{
    const int blk  = blockIdx.x;
    const int head = blk & 15;
    const int n    = blk >> 4;
    const int b    = n / HWP;
    const int hw   = n - b * HWP;
    const size_t base_tok = (size_t)b * (TT * HWP) + hw;

    __shared__ float Qs[32][65];
    __shared__ float Ks[32][65];
    __shared__ float Vs[32][64];
    __shared__ float Ss[32][33];

    const int tid = threadIdx.x;

    for (int i = tid; i < 32 * 64; i += 256) {
        const int t = i >> 6, d = i & 63;
        const size_t tok = base_tok + (size_t)t * HWP;
        const __half* p = qkv + tok * EQKV + head * HD + d;
        Qs[t][d] = __half2float(p[0]);
        Ks[t][d] = __half2float(p[1024]);
        Vs[t][d] = __half2float(p[2048]);
    }
    __syncthreads();

    for (int i = tid; i < 2 * 32 * 16; i += 256) {
        const int mat = i >> 9;
        const int rem = i & 511;
        const int t = rem >> 4, j = rem & 15;
        const float freq = powf(10000.0f, -(float)j / 16.0f);
        const float ang = (float)t * freq;
        const float c = cosf(ang), s = sinf(ang);
        float (*P)[65] = mat ? Ks : Qs;
        const float x0 = P[t][2 * j];
        const float x1 = P[t][2 * j + 1];
        P[t][2 * j]     = x0 * c - x1 * s;
        P[t][2 * j + 1] = x1 * c + x0 * s;
    }
    __syncthreads();

    const int r = tid >> 4, c = tid & 15;
    {
        float s00 = 0.f, s01 = 0.f, s10 = 0.f, s11 = 0.f;
#pragma unroll 16
        for (int d = 0; d < 64; d++) {
            const float q0 = Qs[2 * r][d],     q1 = Qs[2 * r + 1][d];
            const float k0 = Ks[2 * c][d],     k1 = Ks[2 * c + 1][d];
            s00 += q0 * k0; s01 += q0 * k1;
            s10 += q1 * k0; s11 += q1 * k1;
        }
        Ss[2 * r][2 * c]         = s00;
        Ss[2 * r][2 * c + 1]     = s01;
        Ss[2 * r + 1][2 * c]     = s10;
        Ss[2 * r + 1][2 * c + 1] = s11;
    }
    __syncthreads();

    const int warp = tid >> 5, lane = tid & 31;
    const float scale = 0.125f;
#pragma unroll
    for (int qi = 0; qi < 4; qi++) {
        const int q = warp * 4 + qi;
        float s = (lane <= q) ? Ss[q][lane] * scale : -INFINITY;
        float m = s;
#pragma unroll
        for (int o = 16; o > 0; o >>= 1)
            m = fmaxf(m, __shfl_xor_sync(0xffffffffu, m, o));
        const float e = expf(s - m);
        float sum = e;
#pragma unroll
        for (int o = 16; o > 0; o >>= 1)
            sum += __shfl_xor_sync(0xffffffffu, sum, o);
        Ss[q][lane] = e / sum;
    }
    __syncthreads();

    float o0[4] = {0.f, 0.f, 0.f, 0.f};
    float o1[4] = {0.f, 0.f, 0.f, 0.f};
#pragma unroll 8
    for (int k = 0; k < 32; k++) {
        const float p0 = Ss[2 * r][k];
        const float p1 = Ss[2 * r + 1][k];
#pragma unroll
        for (int j = 0; j < 4; j++) {
            const float v = Vs[k][4 * c + j];
            o0[j] += p0 * v;
            o1[j] += p1 * v;
        }
    }
#pragma unroll
    for (int i = 0; i < 2; i++) {
        const int t = 2 * r + i;
        const size_t tok = base_tok + (size_t)t * HWP;
        const size_t base = tok * EO + head * HD + 4 * c;
        const float* src = i ? o1 : o0;
        __half h[4] = {__float2half(src[0]), __float2half(src[1]),
                       __float2half(src[2]), __float2half(src[3])};
        *(uint64_t*)(att + base) = *(const uint64_t*)h;
    }
}

// ---------------------------------------------------------------------------
extern "C" void kernel_launch(void* const* d_in, const int* in_sizes, int n_in,
                              void* d_out, int out_size)
{
    const float* x     = (const float*)d_in[0];
    const float* w_qkv = (const float*)d_in[1];
    const float* w_out = (const float*)d_in[2];
    const float* b_out = (const float*)d_in[3];
    float* out = (float*)d_out;

    void *qkv_p, *x16_p, *wq_p, *wo_p, *att_p;
    cudaGetSymbolAddress(&qkv_p, g_qkv);
    cudaGetSymbolAddress(&x16_p, g_x16);
    cudaGetSymbolAddress(&wq_p,  g_wq);
    cudaGetSymbolAddress(&wo_p,  g_wo);
    cudaGetSymbolAddress(&att_p, g_att);

    __half *qkv = (__half*)qkv_p;
    __half *x16 = (__half*)x16_p;
    __half *wq = (__half*)wq_p, *wo = (__half*)wo_p;
    __half *att = (__half*)att_p;

    cudaFuncSetAttribute(gemm_f16<true>,  cudaFuncAttributeMaxDynamicSharedMemorySize, GSMEM_SZ);
    cudaFuncSetAttribute(gemm_f16<false>, cudaFuncAttributeMaxDynamicSharedMemorySize, GSMEM_SZ);

    // 0) convert x and weights to fp16
    {
        int n4 = (MTOK * DIM) / 4;
        cvt_kernel<<<(n4 + 255) / 256, 256>>>(x, x16, n4);
        n4 = (EQKV * DIM) / 4;
        cvt_kernel<<<(n4 + 255) / 256, 256>>>(w_qkv, wq, n4);
        n4 = (DIM * DIM) / 4;
        cvt_kernel<<<(n4 + 255) / 256, 256>>>(w_out, wo, n4);
    }
    // 1) QKV projection (1-term fp16, fp16 out): qkv[token][3072] = x x w_qkv^T
    {
        dim3 grid(EQKV / 128, MTOK / 128);   // x = chan tiles (W L2-resident), y = token tiles
        gemm_f16<true><<<grid, 256, GSMEM_SZ>>>(wq, x16, qkv, nullptr, EQKV, DIM);
    }
    // 2) RoPE + causal attention (fp16 in/out, fp32 math)
    {
        attn_kernel<<<(BB * HWP) * HEADS, 256>>>(qkv, att);
    }
    // 3) Output projection + bias (1-term, fp32 out): out = att x w_out^T + b
    {
        dim3 grid(DIM / 128, MTOK / 128);
        gemm_f16<false><<<grid, 256, GSMEM_SZ>>>(wo, att, out, b_out, DIM, DIM);
    }
}